// round 1
// baseline (speedup 1.0000x reference)
#include <cuda_runtime.h>

// SinkhornScorer fused kernel for GB300 (sm_103a).
// One CTA per batch element. Phases:
//   A) per-row stats (l2 norm + LayerNorm-dot for dustbin alphas), single pass
//   B) 64x64x256 fp32 GEMM (raw dot products), smem-staged, XOR-swizzled
//   C) couplings C = 10 * cos_sim (+ dustbins), K = exp(C)
//   D) 20 Sinkhorn iterations in LINEAR domain (scaling vectors a, b)
//   E) matching = C + log a + log b + log(128); score = 128 * sum K a b C
//
// Linear-domain Sinkhorn is mathematically identical to the reference's
// log-domain loop (u = log a, v = log b), but replaces ~692M exp ops with FMAs.

namespace {
constexpr int H   = 256;
constexpr int NN  = 64;     // NX == NY
constexpr int NP  = 65;     // with dustbin
constexpr float LOG128 = 4.852030263919617f;   // log(128)
constexpr float MU_IN  = 0.0078125f;           // 1/128
constexpr float MU_DB  = 0.5f;                 // 64/128

__device__ __forceinline__ float warp_sum(float v) {
#pragma unroll
    for (int o = 16; o; o >>= 1) v += __shfl_xor_sync(0xffffffffu, v, o);
    return v;
}
}  // namespace

__global__ void __launch_bounds__(256) sinkhorn_fused_kernel(
    const float* __restrict__ x,      // (B, 64, 256)
    const float* __restrict__ y,      // (B, 64, 256)
    const float* __restrict__ gamma,  // (256,)
    const float* __restrict__ beta,   // (256,)
    const float* __restrict__ wdb,    // (256,1)
    const float* __restrict__ bdb,    // (1,)
    float* __restrict__ out_match,    // (B, 65, 65)
    float* __restrict__ out_score,    // (B,)
    int write_score)
{
    const int b    = blockIdx.x;
    const int t    = threadIdx.x;
    const int lane = t & 31;
    const int wid  = t >> 5;

    // sBuf overlays: GEMM staging (xs 4096 floats | ys 4096 floats),
    // then C (4225 floats) | K (4225 floats). 8450 floats = 33.8 KB.
    __shared__ __align__(16) float sBuf[8450];
    __shared__ __align__(16) float sGw[256];   // gamma*w
    __shared__ float sScale[128];              // 1/||row|| for x rows then y rows
    __shared__ float sAlpha[128];              // dustbin alphas, x rows then y rows
    __shared__ float sAv[NP], sBv[NP], sLa[NP], sLb[NP];
    __shared__ float sRed[16];
    __shared__ float sSgw, sSbw;

    // ---- constants: gw[h] = gamma*w; S_gw = sum gw; S_bw = sum beta*w + b_db ----
    {
        float gwv = gamma[t] * wdb[t];
        float bwv = beta[t] * wdb[t];
        sGw[t] = gwv;
        gwv = warp_sum(gwv);
        bwv = warp_sum(bwv);
        if (lane == 0) { sRed[wid] = gwv; sRed[8 + wid] = bwv; }
    }
    __syncthreads();
    if (t == 0) {
        float a = 0.f, c = 0.f;
#pragma unroll
        for (int i = 0; i < 8; i++) { a += sRed[i]; c += sRed[8 + i]; }
        sSgw = a;
        sSbw = c + bdb[0];
    }
    __syncthreads();

    const float* xb = x + (size_t)b * NN * H;
    const float* yb = y + (size_t)b * NN * H;

    // ---- Phase A: per-row stats (one warp per row, 16 rows per warp) ----
    {
        const float4* gw4 = (const float4*)sGw;
        for (int rr = wid; rr < 128; rr += 8) {
            const float4* rp4 =
                (const float4*)((rr < 64) ? (xb + rr * H) : (yb + (rr - 64) * H));
            float s1 = 0.f, s2 = 0.f, s3 = 0.f;
#pragma unroll
            for (int q = 0; q < 2; q++) {
                float4 v = rp4[lane + 32 * q];
                float4 g = gw4[lane + 32 * q];
                s1 += (v.x + v.y) + (v.z + v.w);
                s2 += v.x * v.x + v.y * v.y + v.z * v.z + v.w * v.w;
                s3 += v.x * g.x + v.y * g.y + v.z * g.z + v.w * g.w;
            }
            s1 = warp_sum(s1);
            s2 = warp_sum(s2);
            s3 = warp_sum(s3);
            if (lane == 0) {
                sScale[rr] = 1.0f / fmaxf(sqrtf(s2), 1e-12f);
                float mu      = s1 * (1.0f / 256.0f);
                float var     = s2 * (1.0f / 256.0f) - mu * mu;
                float inv_std = rsqrtf(var + 1e-5f);
                sAlpha[rr] = tanhf(inv_std * (s3 - mu * sSgw) + sSbw);
            }
        }
    }
    __syncthreads();

    // ---- Phase B: GEMM  scores_raw[i][j] = sum_k x[i][k] * y[j][k] ----
    // smem layout (per matrix): float4 units, [row][16], column index XOR-swizzled
    // by (row>>2)&15 so per-warp loads spread across banks.
    float4* xs4 = (float4*)sBuf;           // rows 0..63
    float4* ys4 = (float4*)(sBuf + 4096);  // rows 0..63
    const int ty = t >> 4;   // 0..15 -> i-tile
    const int tx = t & 15;   // 0..15 -> j-tile
    float acc[4][4] = {};

    const float4* xg = (const float4*)xb;   // 64 float4 per row
    const float4* yg = (const float4*)yb;

    for (int kc = 0; kc < 4; kc++) {
        __syncthreads();
#pragma unroll
        for (int q = 0; q < 4; q++) {
            int idx = t + 256 * q;        // 0..1023
            int row = idx >> 4;
            int c4  = idx & 15;
            int sw  = c4 ^ ((row >> 2) & 15);
            xs4[row * 16 + sw] = xg[row * 64 + kc * 16 + c4];
            ys4[row * 16 + sw] = yg[row * 64 + kc * 16 + c4];
        }
        __syncthreads();
#pragma unroll
        for (int k4 = 0; k4 < 16; k4++) {
            float4 xv[4], yv[4];
#pragma unroll
            for (int ii = 0; ii < 4; ii++)
                xv[ii] = xs4[(ty * 4 + ii) * 16 + (k4 ^ ty)];
#pragma unroll
            for (int jj = 0; jj < 4; jj++)
                yv[jj] = ys4[(tx * 4 + jj) * 16 + (k4 ^ tx)];
#pragma unroll
            for (int ii = 0; ii < 4; ii++)
#pragma unroll
                for (int jj = 0; jj < 4; jj++) {
                    float a = acc[ii][jj];
                    a = fmaf(xv[ii].x, yv[jj].x, a);
                    a = fmaf(xv[ii].y, yv[jj].y, a);
                    a = fmaf(xv[ii].z, yv[jj].z, a);
                    a = fmaf(xv[ii].w, yv[jj].w, a);
                    acc[ii][jj] = a;
                }
        }
    }
    __syncthreads();   // all xs/ys reads done; safe to overlay C/K

    // ---- Phase C: couplings C (log domain) and K = exp(C) ----
    float* C = sBuf;
    float* K = sBuf + 4225;
#pragma unroll
    for (int ii = 0; ii < 4; ii++) {
#pragma unroll
        for (int jj = 0; jj < 4; jj++) {
            int i = ty * 4 + ii, j = tx * 4 + jj;
            float c = acc[ii][jj] * sScale[i] * sScale[64 + j] * 10.0f;
            C[i * NP + j] = c;
            K[i * NP + j] = __expf(c);
        }
    }
    if (t < 64) {
        float cx = 10.0f * sAlpha[t];          // alpha_x dustbin column
        C[t * NP + 64] = cx;  K[t * NP + 64] = __expf(cx);
        float cy = 10.0f * sAlpha[64 + t];     // alpha_y dustbin row
        C[64 * NP + t] = cy;  K[64 * NP + t] = __expf(cy);
    }
    if (t == 0) { C[64 * NP + 64] = -1000.0f; K[64 * NP + 64] = 0.0f; }
    if (t < NP) sBv[t] = 1.0f;                 // v = 0  ->  b = 1
    __syncthreads();

    // ---- Phase D: Sinkhorn, linear domain (nu == mu since m == n) ----
    const float mu_t = (t < 64) ? MU_IN : MU_DB;
    for (int it = 0; it < 20; it++) {
        if (t < NP) {
            const float* Kr = K + t * NP;      // stride 65 -> conflict-free
            float a0 = 0.f, a1 = 0.f, a2 = 0.f, a3 = 0.f;
#pragma unroll
            for (int j = 0; j < 64; j += 4) {
                a0 = fmaf(Kr[j + 0], sBv[j + 0], a0);
                a1 = fmaf(Kr[j + 1], sBv[j + 1], a1);
                a2 = fmaf(Kr[j + 2], sBv[j + 2], a2);
                a3 = fmaf(Kr[j + 3], sBv[j + 3], a3);
            }
            float sum = ((a0 + a1) + (a2 + a3)) + Kr[64] * sBv[64];
            sAv[t] = mu_t / sum;
        }
        __syncthreads();
        if (t < NP) {
            float a0 = 0.f, a1 = 0.f, a2 = 0.f, a3 = 0.f;
#pragma unroll
            for (int i = 0; i < 64; i += 4) {
                a0 = fmaf(K[(i + 0) * NP + t], sAv[i + 0], a0);
                a1 = fmaf(K[(i + 1) * NP + t], sAv[i + 1], a1);
                a2 = fmaf(K[(i + 2) * NP + t], sAv[i + 2], a2);
                a3 = fmaf(K[(i + 3) * NP + t], sAv[i + 3], a3);
            }
            float sum = ((a0 + a1) + (a2 + a3)) + K[64 * NP + t] * sAv[64];
            sBv[t] = mu_t / sum;
        }
        __syncthreads();
    }

    // ---- Phase E: outputs ----
    if (t < NP) { sLa[t] = logf(sAv[t]); sLb[t] = logf(sBv[t]); }
    __syncthreads();

    float* om = out_match + (size_t)b * (NP * NP);
    for (int c = t; c < NP * NP; c += 256) {
        int i = c / NP;
        int j = c - i * NP;
        om[c] = C[c] + sLa[i] + sLb[j] + LOG128;
    }

    if (write_score) {
        // score = (1/temp) * sum exp(matching) * s = sum_{i,j<64} K*a*b*128 * C
        float p = 0.f;
        for (int c = t; c < 64 * 64; c += 256) {
            int i = c >> 6, j = c & 63;
            int idx = i * NP + j;
            p += K[idx] * C[idx] * sAv[i] * sBv[j];
        }
        p = warp_sum(p);
        if (lane == 0) sRed[wid] = p;
        __syncthreads();
        if (t == 0) {
            float s = 0.f;
#pragma unroll
            for (int i = 0; i < 8; i++) s += sRed[i];
            out_score[b] = s * 128.0f;
        }
    }
}

extern "C" void kernel_launch(void* const* d_in, const int* in_sizes, int n_in,
                              void* d_out, int out_size) {
    const float* x     = (const float*)d_in[0];
    const float* y     = (const float*)d_in[1];
    const float* gamma = (const float*)d_in[2];
    const float* beta  = (const float*)d_in[3];
    const float* wdb   = (const float*)d_in[4];
    const float* bdb   = (const float*)d_in[5];

    int B = in_sizes[0] / (NN * H);                 // 4096
    size_t msz = (size_t)B * NP * NP;               // matching elements
    float* out_match = (float*)d_out;
    float* out_score = (float*)d_out + msz;
    int write_score = ((size_t)out_size >= msz + (size_t)B) ? 1 : 0;

    sinkhorn_fused_kernel<<<B, 256>>>(x, y, gamma, beta, wdb, bdb,
                                      out_match, out_score, write_score);
}